// round 1
// baseline (speedup 1.0000x reference)
#include <cuda_runtime.h>
#include <cstddef>

#define D_DIM 512
#define AGENTS 64
#define NBATCH 512
#define MTOT (NBATCH * AGENTS)   // 32768

// ---------------- scratch (device globals: allocation-free) ----------------
__device__ float g_X [MTOT * D_DIM];
__device__ float g_T [MTOT * D_DIM];
__device__ float g_VO[MTOT * D_DIM];
__device__ float g_RO[MTOT * D_DIM];
__device__ float g_Wqk[D_DIM * D_DIM];
__device__ float g_Wvo[D_DIM * D_DIM];
__device__ float g_Wro[D_DIM * D_DIM];
__device__ float g_bvo[D_DIM];
__device__ float g_bro[D_DIM];
__device__ float g_gv [D_DIM];

// ---------------- vector precompute: bvo = bv@Wo, bro = br@Wo + bo, g = Wk@bq
__global__ void vec_pre_k(const float* __restrict__ Wo,
                          const float* __restrict__ bv,
                          const float* __restrict__ br,
                          const float* __restrict__ bo,
                          const float* __restrict__ Wk,
                          const float* __restrict__ bq,
                          float* __restrict__ bvo,
                          float* __restrict__ bro,
                          float* __restrict__ gv)
{
    int j = threadIdx.x;
    if (j < D_DIM) {
        float s1 = 0.f, s2 = 0.f;
        for (int d = 0; d < D_DIM; ++d) {
            float w = Wo[d * D_DIM + j];
            s1 += bv[d] * w;
            s2 += br[d] * w;
        }
        bvo[j] = s1;
        bro[j] = s2 + bo[j];
        float s3 = 0.f;
        const float* wk = Wk + (size_t)j * D_DIM;
        for (int t = 0; t < D_DIM; ++t) s3 += wk[t] * bq[t];
        gv[j] = s3;
    }
}

// ---------------- SGEMM: C[M,N] = A[M,K] @ op(B) (+bias) (relu) ----------------
// TRANSB: B given as [N,K] row-major (C = A @ B^T), else B is [K,N] row-major.
// BM=BN=128, BK=16, 256 threads, 8x8 microtile, register-prefetch pipeline.
template<bool TRANSB, bool BIAS, bool RELU>
__global__ __launch_bounds__(256, 2)
void sgemm_k(const float* __restrict__ A, const float* __restrict__ B,
             const float* __restrict__ bias, float* __restrict__ C,
             int M, int N, int K)
{
    constexpr int BM = 128, BN = 128, BK = 16;
    __shared__ __align__(16) float As[BK][BM + 4];
    __shared__ __align__(16) float Bs[BK][BN + 4];

    const int tid = threadIdx.x;
    const int tx  = tid & 15;      // col group
    const int ty  = tid >> 4;      // row group
    const int m0  = blockIdx.y * BM;
    const int n0  = blockIdx.x * BN;

    const int a_row = tid >> 2;          // 0..63
    const int a_c4  = (tid & 3) * 4;     // 0,4,8,12 (k offset)
    const int b_row = tid >> 4;          // 0..15 (k)
    const int b_col = (tid & 15) * 4;    // 0..60

    float acc[8][8];
#pragma unroll
    for (int i = 0; i < 8; ++i)
#pragma unroll
        for (int j = 0; j < 8; ++j) acc[i][j] = 0.f;

    const int NT = K / BK;
    float4 pa0, pa1, pb0, pb1;

#define SG_LOAD(KT) do {                                                          \
        const int kk = (KT) * BK;                                                \
        pa0 = *(const float4*)(A + (size_t)(m0 + a_row)      * K + kk + a_c4);   \
        pa1 = *(const float4*)(A + (size_t)(m0 + a_row + 64) * K + kk + a_c4);   \
        if (TRANSB) {                                                             \
            pb0 = *(const float4*)(B + (size_t)(n0 + a_row)      * K + kk + a_c4);\
            pb1 = *(const float4*)(B + (size_t)(n0 + a_row + 64) * K + kk + a_c4);\
        } else {                                                                  \
            pb0 = *(const float4*)(B + (size_t)(kk + b_row) * N + n0 + b_col);    \
            pb1 = *(const float4*)(B + (size_t)(kk + b_row) * N + n0 + b_col + 64);\
        }                                                                         \
    } while (0)

#define SG_STORE() do {                                                            \
        As[a_c4 + 0][a_row] = pa0.x; As[a_c4 + 1][a_row] = pa0.y;                 \
        As[a_c4 + 2][a_row] = pa0.z; As[a_c4 + 3][a_row] = pa0.w;                 \
        As[a_c4 + 0][a_row + 64] = pa1.x; As[a_c4 + 1][a_row + 64] = pa1.y;       \
        As[a_c4 + 2][a_row + 64] = pa1.z; As[a_c4 + 3][a_row + 64] = pa1.w;       \
        if (TRANSB) {                                                              \
            Bs[a_c4 + 0][a_row] = pb0.x; Bs[a_c4 + 1][a_row] = pb0.y;             \
            Bs[a_c4 + 2][a_row] = pb0.z; Bs[a_c4 + 3][a_row] = pb0.w;             \
            Bs[a_c4 + 0][a_row + 64] = pb1.x; Bs[a_c4 + 1][a_row + 64] = pb1.y;   \
            Bs[a_c4 + 2][a_row + 64] = pb1.z; Bs[a_c4 + 3][a_row + 64] = pb1.w;   \
        } else {                                                                   \
            *(float4*)&Bs[b_row][b_col]      = pb0;                                \
            *(float4*)&Bs[b_row][b_col + 64] = pb1;                                \
        }                                                                          \
    } while (0)

    SG_LOAD(0);
    SG_STORE();
    __syncthreads();

    for (int kt = 0; kt < NT; ++kt) {
        if (kt + 1 < NT) SG_LOAD(kt + 1);

#pragma unroll
        for (int k = 0; k < BK; ++k) {
            float4 av0 = *(const float4*)&As[k][ty * 8];
            float4 av1 = *(const float4*)&As[k][ty * 8 + 4];
            float4 bv0 = *(const float4*)&Bs[k][tx * 8];
            float4 bv1 = *(const float4*)&Bs[k][tx * 8 + 4];
            float a[8] = {av0.x, av0.y, av0.z, av0.w, av1.x, av1.y, av1.z, av1.w};
            float b[8] = {bv0.x, bv0.y, bv0.z, bv0.w, bv1.x, bv1.y, bv1.z, bv1.w};
#pragma unroll
            for (int i = 0; i < 8; ++i)
#pragma unroll
                for (int j = 0; j < 8; ++j)
                    acc[i][j] += a[i] * b[j];
        }
        __syncthreads();
        if (kt + 1 < NT) {
            SG_STORE();
            __syncthreads();
        }
    }

    float bl[8];
    if (BIAS) {
        float4 bb0 = *(const float4*)(bias + n0 + tx * 8);
        float4 bb1 = *(const float4*)(bias + n0 + tx * 8 + 4);
        bl[0]=bb0.x; bl[1]=bb0.y; bl[2]=bb0.z; bl[3]=bb0.w;
        bl[4]=bb1.x; bl[5]=bb1.y; bl[6]=bb1.z; bl[7]=bb1.w;
    }

#pragma unroll
    for (int i = 0; i < 8; ++i) {
        const int row = m0 + ty * 8 + i;
        float v[8];
#pragma unroll
        for (int j = 0; j < 8; ++j) {
            float t = acc[i][j];
            if (BIAS) t += bl[j];
            if (RELU) t = fmaxf(t, 0.f);
            v[j] = t;
        }
        float4 o0 = {v[0], v[1], v[2], v[3]};
        float4 o1 = {v[4], v[5], v[6], v[7]};
        *(float4*)(C + (size_t)row * N + n0 + tx * 8)     = o0;
        *(float4*)(C + (size_t)row * N + n0 + tx * 8 + 4) = o1;
    }
#undef SG_LOAD
#undef SG_STORE
}

// ---------------- per-batch attention + epilogue ----------------
// scores[a][c] = sum_d T[a][d] X[c][d] + w[c],  w[c] = X[c]·g
// attn = softmax rows; OUT = relu(attn @ VO + RO)   (biases folded into VO/RO)
__global__ __launch_bounds__(256, 2)
void attn_k(const float* __restrict__ X, const float* __restrict__ T,
            const float* __restrict__ VO, const float* __restrict__ RO,
            const float* __restrict__ gv, float* __restrict__ OUT)
{
    __shared__ float sc[64][65];
    __shared__ __align__(16) float sbuf[64 * 68];   // TT[32][68]+XT[32][68] / VOt[64][68]
    __shared__ float gsh[512];
    __shared__ float wpart[4][64];
    __shared__ float wsh[64];

    const int b = blockIdx.x;
    const size_t base = (size_t)b * 64 * 512;
    const float* Xb  = X  + base;
    const float* Tb  = T  + base;
    const float* VOb = VO + base;
    const float* ROb = RO + base;
    float*       Ob  = OUT + base;

    const int tid = threadIdx.x;
    const int tx = tid & 15, ty = tid >> 4;

    gsh[tid]       = gv[tid];
    gsh[tid + 256] = gv[tid + 256];
    __syncthreads();

    // w partials: 4 partitions of 128 over D
    {
        const int r = tid & 63, p = tid >> 6;
        const float* xr = Xb + r * 512 + p * 128;
        const float* gp = gsh + p * 128;
        float s = 0.f;
#pragma unroll 8
        for (int d = 0; d < 128; ++d) s += xr[d] * gp[d];
        wpart[p][r] = s;
    }

    // scores: 64x64, K=512, k-tiles of 32, transposed smem staging
    float acc[4][4];
#pragma unroll
    for (int i = 0; i < 4; ++i)
#pragma unroll
        for (int j = 0; j < 4; ++j) acc[i][j] = 0.f;

    float* TT = sbuf;              // [32][68]
    float* XT = sbuf + 32 * 68;    // [32][68]

    for (int kt = 0; kt < 16; ++kt) {
        __syncthreads();
#pragma unroll
        for (int q = 0; q < 2; ++q) {
            const int idx = tid + q * 256;
            const int row = idx >> 3;
            const int c4  = (idx & 7) * 4;
            float4 v = *(const float4*)(Tb + row * 512 + kt * 32 + c4);
            TT[(c4 + 0) * 68 + row] = v.x; TT[(c4 + 1) * 68 + row] = v.y;
            TT[(c4 + 2) * 68 + row] = v.z; TT[(c4 + 3) * 68 + row] = v.w;
            float4 u = *(const float4*)(Xb + row * 512 + kt * 32 + c4);
            XT[(c4 + 0) * 68 + row] = u.x; XT[(c4 + 1) * 68 + row] = u.y;
            XT[(c4 + 2) * 68 + row] = u.z; XT[(c4 + 3) * 68 + row] = u.w;
        }
        __syncthreads();
#pragma unroll
        for (int k = 0; k < 32; ++k) {
            float4 av = *(const float4*)&TT[k * 68 + ty * 4];
            float4 bv = *(const float4*)&XT[k * 68 + tx * 4];
            float a[4] = {av.x, av.y, av.z, av.w};
            float bb[4] = {bv.x, bv.y, bv.z, bv.w};
#pragma unroll
            for (int i = 0; i < 4; ++i)
#pragma unroll
                for (int j = 0; j < 4; ++j)
                    acc[i][j] += a[i] * bb[j];
        }
    }
    __syncthreads();
    if (tid < 64)
        wsh[tid] = wpart[0][tid] + wpart[1][tid] + wpart[2][tid] + wpart[3][tid];
    __syncthreads();
#pragma unroll
    for (int i = 0; i < 4; ++i)
#pragma unroll
        for (int j = 0; j < 4; ++j)
            sc[ty * 4 + i][tx * 4 + j] = acc[i][j] + wsh[tx * 4 + j];
    __syncthreads();

    // softmax: one thread per row (64 rows)
    if (tid < 64) {
        float m = -1e30f;
#pragma unroll 8
        for (int c = 0; c < 64; ++c) m = fmaxf(m, sc[tid][c]);
        float s = 0.f;
#pragma unroll 8
        for (int c = 0; c < 64; ++c) { float e = expf(sc[tid][c] - m); sc[tid][c] = e; s += e; }
        const float inv = 1.f / s;
#pragma unroll 8
        for (int c = 0; c < 64; ++c) sc[tid][c] *= inv;
    }

    // OUT = relu(attn @ VO + RO), N-tiles of 64
    float* VOt = sbuf;   // [64][68]
    for (int nt = 0; nt < 8; ++nt) {
        __syncthreads();
#pragma unroll
        for (int q = 0; q < 4; ++q) {
            const int idx = tid + q * 256;
            const int row = idx >> 4;
            const int c4  = (idx & 15) * 4;
            *(float4*)&VOt[row * 68 + c4] =
                *(const float4*)(VOb + row * 512 + nt * 64 + c4);
        }
        __syncthreads();

        float o[4][4];
#pragma unroll
        for (int i = 0; i < 4; ++i)
#pragma unroll
            for (int j = 0; j < 4; ++j) o[i][j] = 0.f;

#pragma unroll
        for (int k = 0; k < 64; ++k) {
            float a0 = sc[ty * 4 + 0][k];
            float a1 = sc[ty * 4 + 1][k];
            float a2 = sc[ty * 4 + 2][k];
            float a3 = sc[ty * 4 + 3][k];
            float4 bv = *(const float4*)&VOt[k * 68 + tx * 4];
            o[0][0] += a0 * bv.x; o[0][1] += a0 * bv.y; o[0][2] += a0 * bv.z; o[0][3] += a0 * bv.w;
            o[1][0] += a1 * bv.x; o[1][1] += a1 * bv.y; o[1][2] += a1 * bv.z; o[1][3] += a1 * bv.w;
            o[2][0] += a2 * bv.x; o[2][1] += a2 * bv.y; o[2][2] += a2 * bv.z; o[2][3] += a2 * bv.w;
            o[3][0] += a3 * bv.x; o[3][1] += a3 * bv.y; o[3][2] += a3 * bv.z; o[3][3] += a3 * bv.w;
        }
#pragma unroll
        for (int i = 0; i < 4; ++i) {
            const int row = ty * 4 + i;
            float4 rv = *(const float4*)(ROb + row * 512 + nt * 64 + tx * 4);
            float4 ov;
            ov.x = fmaxf(o[i][0] + rv.x, 0.f);
            ov.y = fmaxf(o[i][1] + rv.y, 0.f);
            ov.z = fmaxf(o[i][2] + rv.z, 0.f);
            ov.w = fmaxf(o[i][3] + rv.w, 0.f);
            *(float4*)(Ob + row * 512 + nt * 64 + tx * 4) = ov;
        }
    }
}

// ---------------- launch ----------------
extern "C" void kernel_launch(void* const* d_in, const int* in_sizes, int n_in,
                              void* d_out, int out_size)
{
    const float* inp = (const float*)d_in[0];
    const float* Win = (const float*)d_in[1];
    const float* bin = (const float*)d_in[2];
    const float* Wq  = (const float*)d_in[3];
    const float* bq  = (const float*)d_in[4];
    const float* Wk  = (const float*)d_in[5];
    // d_in[6] = b_k : provably unused (drops out of softmax)
    const float* Wv  = (const float*)d_in[7];
    const float* bv  = (const float*)d_in[8];
    const float* Wr  = (const float*)d_in[9];
    const float* br  = (const float*)d_in[10];
    const float* Wo  = (const float*)d_in[11];
    const float* bo  = (const float*)d_in[12];
    float* out = (float*)d_out;

    float *X, *T, *VO, *RO, *Wqk, *Wvo, *Wro, *bvo, *bro, *gv;
    cudaGetSymbolAddress((void**)&X,   g_X);
    cudaGetSymbolAddress((void**)&T,   g_T);
    cudaGetSymbolAddress((void**)&VO,  g_VO);
    cudaGetSymbolAddress((void**)&RO,  g_RO);
    cudaGetSymbolAddress((void**)&Wqk, g_Wqk);
    cudaGetSymbolAddress((void**)&Wvo, g_Wvo);
    cudaGetSymbolAddress((void**)&Wro, g_Wro);
    cudaGetSymbolAddress((void**)&bvo, g_bvo);
    cudaGetSymbolAddress((void**)&bro, g_bro);
    cudaGetSymbolAddress((void**)&gv,  g_gv);

    const dim3 bs(256);
    const dim3 gW(D_DIM / 128, D_DIM / 128);      // 4 x 4
    const dim3 gBig(D_DIM / 128, MTOT / 128);     // 4 x 256

    // weight precompute
    vec_pre_k<<<1, 512>>>(Wo, bv, br, bo, Wk, bq, bvo, bro, gv);
    sgemm_k<true,  false, false><<<gW, bs>>>(Wq, Wk, nullptr, Wqk, D_DIM, D_DIM, D_DIM); // Wq@Wk^T
    sgemm_k<false, false, false><<<gW, bs>>>(Wv, Wo, nullptr, Wvo, D_DIM, D_DIM, D_DIM);
    sgemm_k<false, false, false><<<gW, bs>>>(Wr, Wo, nullptr, Wro, D_DIM, D_DIM, D_DIM);

    // main GEMMs
    sgemm_k<false, true,  true ><<<gBig, bs>>>(inp, Win, bin, X,  MTOT, D_DIM, D_DIM);
    sgemm_k<false, false, false><<<gBig, bs>>>(X,   Wqk, nullptr, T,  MTOT, D_DIM, D_DIM);
    sgemm_k<false, true,  false><<<gBig, bs>>>(X,   Wvo, bvo,     VO, MTOT, D_DIM, D_DIM);
    sgemm_k<false, true,  false><<<gBig, bs>>>(X,   Wro, bro,     RO, MTOT, D_DIM, D_DIM);

    // attention + epilogue
    attn_k<<<NBATCH, bs>>>(X, T, VO, RO, gv, out);
}

// round 3
// speedup vs baseline: 2.0491x; 2.0491x over previous
#include <cuda_runtime.h>
#include <cuda_bf16.h>
#include <cstdint>
#include <cstddef>

#define D_DIM 512
#define AGENTS 64
#define NBATCH 512
#define MTOT (NBATCH * AGENTS)   // 32768
#define NTVR 1536

// ---------------- scratch (device globals: allocation-free) ----------------
__device__ __align__(128) float           g_X   [MTOT * D_DIM];
__device__ __align__(128) __nv_bfloat16   g_Xhi [MTOT * D_DIM];
__device__ __align__(128) __nv_bfloat16   g_Xlo [MTOT * D_DIM];
__device__ __align__(128) __nv_bfloat16   g_Ihi [MTOT * D_DIM];
__device__ __align__(128) __nv_bfloat16   g_Ilo [MTOT * D_DIM];
__device__ __align__(128) float           g_TVR [MTOT * NTVR];
__device__ __align__(128) float           g_Wqk [D_DIM * D_DIM];
__device__ __align__(128) float           g_Wvo [D_DIM * D_DIM];
__device__ __align__(128) float           g_Wro [D_DIM * D_DIM];
__device__ __align__(128) __nv_bfloat16   g_WinT_hi[D_DIM * D_DIM];
__device__ __align__(128) __nv_bfloat16   g_WinT_lo[D_DIM * D_DIM];
__device__ __align__(128) __nv_bfloat16   g_WbT_hi [NTVR * D_DIM];
__device__ __align__(128) __nv_bfloat16   g_WbT_lo [NTVR * D_DIM];
__device__ __align__(128) float           g_gv  [D_DIM];
__device__ __align__(128) float           g_bias2[NTVR];

#define SWZ(o) ((o) ^ (((o) >> 3) & 0x70))

__device__ __forceinline__ uint32_t smem_u32(const void* p) {
    uint32_t a;
    asm("{ .reg .u64 t; cvta.to.shared.u64 t, %1; cvt.u32.u64 %0, t; }" : "=r"(a) : "l"(p));
    return a;
}
__device__ __forceinline__ void split1(float x, __nv_bfloat16& h, __nv_bfloat16& l) {
    h = __float2bfloat16(x);
    l = __float2bfloat16(x - __bfloat162float(h));
}
__device__ __forceinline__ void ldsm4(uint32_t* r, uint32_t addr) {
    asm volatile("ldmatrix.sync.aligned.m8n8.x4.shared.b16 {%0,%1,%2,%3}, [%4];"
                 : "=r"(r[0]), "=r"(r[1]), "=r"(r[2]), "=r"(r[3]) : "r"(addr));
}
__device__ __forceinline__ void mma16816(float* d, const uint32_t* a, uint32_t b0, uint32_t b1) {
    asm volatile(
        "mma.sync.aligned.m16n8k16.row.col.f32.bf16.bf16.f32 "
        "{%0,%1,%2,%3}, {%4,%5,%6,%7}, {%8,%9}, {%0,%1,%2,%3};"
        : "+f"(d[0]), "+f"(d[1]), "+f"(d[2]), "+f"(d[3])
        : "r"(a[0]), "r"(a[1]), "r"(a[2]), "r"(a[3]), "r"(b0), "r"(b1));
}
__device__ __forceinline__ void cpasync16(uint32_t dst, const void* src) {
    asm volatile("cp.async.cg.shared.global [%0], [%1], 16;" :: "r"(dst), "l"(src));
}
#define CP_COMMIT() asm volatile("cp.async.commit_group;" ::: "memory")
#define CP_WAIT(N)  asm volatile("cp.async.wait_group " #N ";" ::: "memory")

// ---------------- split inputs (fp32 -> bf16 hi/lo) ----------------
__global__ void split_k(const float* __restrict__ src,
                        __nv_bfloat16* __restrict__ hi, __nv_bfloat16* __restrict__ lo, int n4) {
    int i = blockIdx.x * blockDim.x + threadIdx.x;
    if (i >= n4) return;
    float4 v = ((const float4*)src)[i];
    __nv_bfloat16 h0,h1,h2,h3,l0,l1,l2,l3;
    split1(v.x,h0,l0); split1(v.y,h1,l1); split1(v.z,h2,l2); split1(v.w,h3,l3);
    uint32_t ha = (uint32_t)__bfloat16_as_ushort(h0) | ((uint32_t)__bfloat16_as_ushort(h1) << 16);
    uint32_t hb = (uint32_t)__bfloat16_as_ushort(h2) | ((uint32_t)__bfloat16_as_ushort(h3) << 16);
    uint32_t la = (uint32_t)__bfloat16_as_ushort(l0) | ((uint32_t)__bfloat16_as_ushort(l1) << 16);
    uint32_t lb = (uint32_t)__bfloat16_as_ushort(l2) | ((uint32_t)__bfloat16_as_ushort(l3) << 16);
    ((uint2*)hi)[i] = make_uint2(ha, hb);
    ((uint2*)lo)[i] = make_uint2(la, lb);
}

// ---------------- transpose + split weights: W[K,N] -> Wt[n_off+n][k] ----------------
__global__ void tsplit_k(const float* __restrict__ W,
                         __nv_bfloat16* __restrict__ hiT, __nv_bfloat16* __restrict__ loT,
                         int n_off) {
    __shared__ float tle[32][33];
    int tx = threadIdx.x, ty = threadIdx.y;
    int n0 = blockIdx.x * 32, k0 = blockIdx.y * 32;
    tle[ty][tx] = W[(size_t)(k0 + ty) * 512 + n0 + tx];
    __syncthreads();
    float v = tle[tx][ty];                 // W[k0+tx][n0+ty]
    int drow = n_off + n0 + ty, dcol = k0 + tx;
    __nv_bfloat16 h, l; split1(v, h, l);
    hiT[(size_t)drow * 512 + dcol] = h;
    loT[(size_t)drow * 512 + dcol] = l;
}

// ---------------- vector precompute: gv = Wk@bq ; bias2 = {0, bv@Wo, br@Wo+bo} ----------------
__global__ void vec_pre_k(const float* __restrict__ Wo,
                          const float* __restrict__ bv,
                          const float* __restrict__ br,
                          const float* __restrict__ bo,
                          const float* __restrict__ Wk,
                          const float* __restrict__ bq,
                          float* __restrict__ gv,
                          float* __restrict__ bias2) {
    int j = threadIdx.x;
    if (j < D_DIM) {
        float s1 = 0.f, s2 = 0.f;
        for (int d = 0; d < D_DIM; ++d) {
            float w = Wo[d * D_DIM + j];
            s1 += bv[d] * w;
            s2 += br[d] * w;
        }
        float s3 = 0.f;
        const float* wk = Wk + (size_t)j * D_DIM;
        for (int t = 0; t < D_DIM; ++t) s3 += wk[t] * bq[t];
        gv[j] = s3;
        bias2[j] = 0.f;
        bias2[512 + j] = s1;
        bias2[1024 + j] = s2 + bo[j];
    }
}

// ---------------- weight precompute: 3 fp32 512x512x512 GEMMs, 64x64 tiles ----------------
// z=0: Wqk = Wq @ Wk^T ; z=1: Wvo = Wv @ Wo ; z=2: Wro = Wr @ Wo
__global__ __launch_bounds__(256)
void wpre_k(const float* __restrict__ Wq, const float* __restrict__ Wk,
            const float* __restrict__ Wv, const float* __restrict__ Wr,
            const float* __restrict__ Wo,
            float* __restrict__ Wqk, float* __restrict__ Wvo, float* __restrict__ Wro) {
    const int z = blockIdx.z;
    const float* A = (z == 0) ? Wq : ((z == 1) ? Wv : Wr);
    const float* B = (z == 0) ? Wk : Wo;
    float* C = (z == 0) ? Wqk : ((z == 1) ? Wvo : Wro);
    const bool transb = (z == 0);

    __shared__ __align__(16) float As[32][72];
    __shared__ __align__(16) float Bs[32][72];
    const int t = threadIdx.x;
    const int tx = t & 15, ty = t >> 4;
    const int m0 = blockIdx.y * 64, n0 = blockIdx.x * 64;

    float acc[4][4];
#pragma unroll
    for (int i = 0; i < 4; ++i)
#pragma unroll
        for (int j = 0; j < 4; ++j) acc[i][j] = 0.f;

    for (int kt = 0; kt < 16; ++kt) {
        __syncthreads();
#pragma unroll
        for (int i = 0; i < 2; ++i) {
            const int idx = t + i * 256;
            const int row = idx >> 3, c4 = (idx & 7) * 4;
            float4 v = *(const float4*)(A + (size_t)(m0 + row) * 512 + kt * 32 + c4);
            As[c4 + 0][row] = v.x; As[c4 + 1][row] = v.y;
            As[c4 + 2][row] = v.z; As[c4 + 3][row] = v.w;
        }
        if (transb) {
#pragma unroll
            for (int i = 0; i < 2; ++i) {
                const int idx = t + i * 256;
                const int row = idx >> 3, c4 = (idx & 7) * 4;
                float4 v = *(const float4*)(B + (size_t)(n0 + row) * 512 + kt * 32 + c4);
                Bs[c4 + 0][row] = v.x; Bs[c4 + 1][row] = v.y;
                Bs[c4 + 2][row] = v.z; Bs[c4 + 3][row] = v.w;
            }
        } else {
#pragma unroll
            for (int i = 0; i < 2; ++i) {
                const int idx = t + i * 256;
                const int kr = idx >> 4, c4 = (idx & 15) * 4;
                float4 v = *(const float4*)(B + (size_t)(kt * 32 + kr) * 512 + n0 + c4);
                *(float4*)&Bs[kr][c4] = v;
            }
        }
        __syncthreads();
#pragma unroll
        for (int k = 0; k < 32; ++k) {
            float4 av = *(const float4*)&As[k][ty * 4];
            float4 bv = *(const float4*)&Bs[k][tx * 4];
            float a[4] = {av.x, av.y, av.z, av.w};
            float b[4] = {bv.x, bv.y, bv.z, bv.w};
#pragma unroll
            for (int i = 0; i < 4; ++i)
#pragma unroll
                for (int j = 0; j < 4; ++j) acc[i][j] += a[i] * b[j];
        }
    }
#pragma unroll
    for (int i = 0; i < 4; ++i) {
        float4 o = {acc[i][0], acc[i][1], acc[i][2], acc[i][3]};
        *(float4*)(C + (size_t)(m0 + ty * 4 + i) * 512 + n0 + tx * 4) = o;
    }
}

// ---------------- HMMA split-bf16 GEMM ----------------
// C[M, Ntot] = (Ahi+Alo)[M,512] @ (Bhi+Blo)^T[Ntot,512] + bias
// realized as Keff=1536: chunks 0-7: Ahi*Bhi, 8-15: Ahi*Blo, 16-23: Alo*Bhi.
// CTA tile 128x128, BK=64, 8 warps (warp tile 32x64), 2-stage cp.async pipeline.
#define MG_SMEM 65536

template<bool RELU, bool SPLITOUT>
__global__ __launch_bounds__(256)
void mma_gemm(const __nv_bfloat16* __restrict__ Ahi, const __nv_bfloat16* __restrict__ Alo,
              const __nv_bfloat16* __restrict__ Bhi, const __nv_bfloat16* __restrict__ Blo,
              const float* __restrict__ bias, float* __restrict__ C,
              __nv_bfloat16* __restrict__ Chi, __nv_bfloat16* __restrict__ Clo, int Ntot)
{
    extern __shared__ char sm[];
    const uint32_t smA = smem_u32(sm);           // 2 stages x 16KB
    const uint32_t smB = smA + 32768;            // 2 stages x 16KB

    const int t = threadIdx.x;
    const int wid = t >> 5, l = t & 31;
    const int wm = wid >> 1, wn = wid & 1;       // 4x2 warp grid, warp tile 32x64
    const int m0 = blockIdx.y * 128, n0 = blockIdx.x * 128;

    const int arow = l & 15, acol = l >> 4;
    const int brow = (l & 7) + ((l >> 4) & 1) * 8, bcol = (l >> 3) & 1;

    float acc[2][8][4];
#pragma unroll
    for (int mi = 0; mi < 2; ++mi)
#pragma unroll
        for (int ni = 0; ni < 8; ++ni)
#pragma unroll
            for (int q = 0; q < 4; ++q) acc[mi][ni][q] = 0.f;

    const int lrow = t >> 3, lcg = t & 7;
    const uint32_t loff = SWZ((uint32_t)(lrow * 128 + lcg * 16));

    auto load_chunk = [&](int c, int s) {
        const int seg = c >> 3;
        const int kk = (c & 7) * 64;
        const __nv_bfloat16* Asrc = (seg == 2) ? Alo : Ahi;
        const __nv_bfloat16* Bsrc = (seg == 1) ? Blo : Bhi;
        const uint32_t ab = smA + s * 16384;
        const uint32_t bb = smB + s * 16384;
#pragma unroll
        for (int i = 0; i < 4; ++i) {
            const int row = lrow + i * 32;
            const uint32_t off = SWZ((uint32_t)(row * 128 + lcg * 16));
            cpasync16(ab + off, Asrc + (size_t)(m0 + row) * 512 + kk + lcg * 8);
            cpasync16(bb + off, Bsrc + (size_t)(n0 + row) * 512 + kk + lcg * 8);
        }
        CP_COMMIT();
    };

    auto compute = [&](int s) {
        const uint32_t ab = smA + s * 16384;
        const uint32_t bb = smB + s * 16384;
#pragma unroll
        for (int ks = 0; ks < 4; ++ks) {
            uint32_t a[2][4];
#pragma unroll
            for (int mi = 0; mi < 2; ++mi) {
                const int row = wm * 32 + mi * 16 + arow;
                ldsm4(a[mi], ab + SWZ((uint32_t)(row * 128 + (ks * 2 + acol) * 16)));
            }
#pragma unroll
            for (int nb = 0; nb < 4; ++nb) {
                const int row = wn * 64 + nb * 16 + brow;
                uint32_t b[4];
                ldsm4(b, bb + SWZ((uint32_t)(row * 128 + (ks * 2 + bcol) * 16)));
                mma16816(acc[0][nb * 2],     a[0], b[0], b[1]);
                mma16816(acc[1][nb * 2],     a[1], b[0], b[1]);
                mma16816(acc[0][nb * 2 + 1], a[0], b[2], b[3]);
                mma16816(acc[1][nb * 2 + 1], a[1], b[2], b[3]);
            }
        }
    };

    load_chunk(0, 0);
    load_chunk(1, 1);
    CP_WAIT(1);
    __syncthreads();

    for (int c = 0; c < 24; ++c) {
        const int s = c & 1;
        compute(s);
        if (c == 23) break;
        __syncthreads();
        if (c + 2 < 24) { load_chunk(c + 2, s); CP_WAIT(1); }
        else            { CP_WAIT(0); }
        __syncthreads();
    }

    // epilogue
    const int gid = l >> 2, tig = l & 3;
#pragma unroll
    for (int mi = 0; mi < 2; ++mi) {
#pragma unroll
        for (int ni = 0; ni < 8; ++ni) {
            const int row = m0 + wm * 32 + mi * 16 + gid;
            const int col = n0 + wn * 64 + ni * 8 + tig * 2;
            float2 bb = *(const float2*)(bias + col);
            float v0 = acc[mi][ni][0] + bb.x;
            float v1 = acc[mi][ni][1] + bb.y;
            float v2 = acc[mi][ni][2] + bb.x;
            float v3 = acc[mi][ni][3] + bb.y;
            if (RELU) {
                v0 = fmaxf(v0, 0.f); v1 = fmaxf(v1, 0.f);
                v2 = fmaxf(v2, 0.f); v3 = fmaxf(v3, 0.f);
            }
            *(float2*)(C + (size_t)row * Ntot + col)       = make_float2(v0, v1);
            *(float2*)(C + (size_t)(row + 8) * Ntot + col) = make_float2(v2, v3);
            if (SPLITOUT) {
                __nv_bfloat16 h0,h1,h2,h3,l0,l1,l2,l3;
                split1(v0,h0,l0); split1(v1,h1,l1); split1(v2,h2,l2); split1(v3,h3,l3);
                ushort2 hu0 = {__bfloat16_as_ushort(h0), __bfloat16_as_ushort(h1)};
                ushort2 hu1 = {__bfloat16_as_ushort(h2), __bfloat16_as_ushort(h3)};
                ushort2 lu0 = {__bfloat16_as_ushort(l0), __bfloat16_as_ushort(l1)};
                ushort2 lu1 = {__bfloat16_as_ushort(l2), __bfloat16_as_ushort(l3)};
                *(ushort2*)(Chi + (size_t)row * 512 + col)       = hu0;
                *(ushort2*)(Chi + (size_t)(row + 8) * 512 + col) = hu1;
                *(ushort2*)(Clo + (size_t)row * 512 + col)       = lu0;
                *(ushort2*)(Clo + (size_t)(row + 8) * 512 + col) = lu1;
            }
        }
    }
}

// ---------------- per-batch attention + epilogue ----------------
__global__ __launch_bounds__(256, 2)
void attn_k(const float* __restrict__ X, const float* __restrict__ TVR,
            const float* __restrict__ gv, float* __restrict__ OUT)
{
    __shared__ float sc[64][65];
    __shared__ __align__(16) float sbuf[64 * 68];
    __shared__ float gsh[512];
    __shared__ float wpart[4][64];
    __shared__ float wsh[64];

    const int b = blockIdx.x;
    const float* Xb   = X   + (size_t)b * 64 * 512;
    const float* TVRb = TVR + (size_t)b * 64 * NTVR;
    float*       Ob   = OUT + (size_t)b * 64 * 512;

    const int tid = threadIdx.x;
    const int tx = tid & 15, ty = tid >> 4;

    gsh[tid]       = gv[tid];
    gsh[tid + 256] = gv[tid + 256];
    __syncthreads();

    {
        const int r = tid & 63, p = tid >> 6;
        const float* xr = Xb + r * 512 + p * 128;
        const float* gp = gsh + p * 128;
        float s = 0.f;
#pragma unroll 8
        for (int d = 0; d < 128; ++d) s += xr[d] * gp[d];
        wpart[p][r] = s;
    }

    float acc[4][4];
#pragma unroll
    for (int i = 0; i < 4; ++i)
#pragma unroll
        for (int j = 0; j < 4; ++j) acc[i][j] = 0.f;

    float* TT = sbuf;
    float* XT = sbuf + 32 * 68;

    for (int kt = 0; kt < 16; ++kt) {
        __syncthreads();
#pragma unroll
        for (int q = 0; q < 2; ++q) {
            const int idx = tid + q * 256;
            const int row = idx >> 3;
            const int c4  = (idx & 7) * 4;
            float4 v = *(const float4*)(TVRb + row * NTVR + kt * 32 + c4);
            TT[(c4 + 0) * 68 + row] = v.x; TT[(c4 + 1) * 68 + row] = v.y;
            TT[(c4 + 2) * 68 + row] = v.z; TT[(c4 + 3) * 68 + row] = v.w;
            float4 u = *(const float4*)(Xb + row * 512 + kt * 32 + c4);
            XT[(c4 + 0) * 68 + row] = u.x; XT[(c4 + 1) * 68 + row] = u.y;
            XT[(c4 + 2) * 68 + row] = u.z; XT[(c4 + 3) * 68 + row] = u.w;
        }
        __syncthreads();
#pragma unroll
        for (int k = 0; k < 32; ++k) {
            float4 av = *(const float4*)&TT[k * 68 + ty * 4];
            float4 bv = *(const float4*)&XT[k * 68 + tx * 4];
            float a[4]  = {av.x, av.y, av.z, av.w};
            float bb[4] = {bv.x, bv.y, bv.z, bv.w};
#pragma unroll
            for (int i = 0; i < 4; ++i)
#pragma unroll
                for (int j = 0; j < 4; ++j) acc[i][j] += a[i] * bb[j];
        }
    }
    __syncthreads();
    if (tid < 64)
        wsh[tid] = wpart[0][tid] + wpart[1][tid] + wpart[2][tid] + wpart[3][tid];
    __syncthreads();
#pragma unroll
    for (int i = 0; i < 4; ++i)
#pragma unroll
        for (int j = 0; j < 4; ++j)
            sc[ty * 4 + i][tx * 4 + j] = acc[i][j] + wsh[tx * 4 + j];
    __syncthreads();

    if (tid < 64) {
        float m = -1e30f;
#pragma unroll 8
        for (int c = 0; c < 64; ++c) m = fmaxf(m, sc[tid][c]);
        float s = 0.f;
#pragma unroll 8
        for (int c = 0; c < 64; ++c) { float e = expf(sc[tid][c] - m); sc[tid][c] = e; s += e; }
        const float inv = 1.f / s;
#pragma unroll 8
        for (int c = 0; c < 64; ++c) sc[tid][c] *= inv;
    }

    float* VOt = sbuf;
    for (int nt = 0; nt < 8; ++nt) {
        __syncthreads();
#pragma unroll
        for (int q = 0; q < 4; ++q) {
            const int idx = tid + q * 256;
            const int row = idx >> 4;
            const int c4  = (idx & 15) * 4;
            *(float4*)&VOt[row * 68 + c4] =
                *(const float4*)(TVRb + row * NTVR + 512 + nt * 64 + c4);
        }
        __syncthreads();

        float o[4][4];
#pragma unroll
        for (int i = 0; i < 4; ++i)
#pragma unroll
            for (int j = 0; j < 4; ++j) o[i][j] = 0.f;

#pragma unroll
        for (int k = 0; k < 64; ++k) {
            float a0 = sc[ty * 4 + 0][k];
            float a1 = sc[ty * 4 + 1][k];
            float a2 = sc[ty * 4 + 2][k];
            float a3 = sc[ty * 4 + 3][k];
            float4 bv = *(const float4*)&VOt[k * 68 + tx * 4];
            o[0][0] += a0 * bv.x; o[0][1] += a0 * bv.y; o[0][2] += a0 * bv.z; o[0][3] += a0 * bv.w;
            o[1][0] += a1 * bv.x; o[1][1] += a1 * bv.y; o[1][2] += a1 * bv.z; o[1][3] += a1 * bv.w;
            o[2][0] += a2 * bv.x; o[2][1] += a2 * bv.y; o[2][2] += a2 * bv.z; o[2][3] += a2 * bv.w;
            o[3][0] += a3 * bv.x; o[3][1] += a3 * bv.y; o[3][2] += a3 * bv.z; o[3][3] += a3 * bv.w;
        }
#pragma unroll
        for (int i = 0; i < 4; ++i) {
            const int row = ty * 4 + i;
            float4 rv = *(const float4*)(TVRb + row * NTVR + 1024 + nt * 64 + tx * 4);
            float4 ov;
            ov.x = fmaxf(o[i][0] + rv.x, 0.f);
            ov.y = fmaxf(o[i][1] + rv.y, 0.f);
            ov.z = fmaxf(o[i][2] + rv.z, 0.f);
            ov.w = fmaxf(o[i][3] + rv.w, 0.f);
            *(float4*)(Ob + row * 512 + nt * 64 + tx * 4) = ov;
        }
    }
}

// ---------------- launch ----------------
extern "C" void kernel_launch(void* const* d_in, const int* in_sizes, int n_in,
                              void* d_out, int out_size)
{
    const float* inp = (const float*)d_in[0];
    const float* Win = (const float*)d_in[1];
    const float* bin = (const float*)d_in[2];
    const float* Wq  = (const float*)d_in[3];
    const float* bq  = (const float*)d_in[4];
    const float* Wk  = (const float*)d_in[5];
    // d_in[6] = b_k : provably unused (row-constant, drops out of softmax)
    const float* Wv  = (const float*)d_in[7];
    const float* bv  = (const float*)d_in[8];
    const float* Wr  = (const float*)d_in[9];
    const float* br  = (const float*)d_in[10];
    const float* Wo  = (const float*)d_in[11];
    const float* bo  = (const float*)d_in[12];
    float* out = (float*)d_out;

    float *X, *TVR, *Wqk, *Wvo, *Wro, *gv, *bias2;
    __nv_bfloat16 *Xhi, *Xlo, *Ihi, *Ilo, *WinT_hi, *WinT_lo, *WbT_hi, *WbT_lo;
    cudaGetSymbolAddress((void**)&X,       g_X);
    cudaGetSymbolAddress((void**)&TVR,     g_TVR);
    cudaGetSymbolAddress((void**)&Wqk,     g_Wqk);
    cudaGetSymbolAddress((void**)&Wvo,     g_Wvo);
    cudaGetSymbolAddress((void**)&Wro,     g_Wro);
    cudaGetSymbolAddress((void**)&gv,      g_gv);
    cudaGetSymbolAddress((void**)&bias2,   g_bias2);
    cudaGetSymbolAddress((void**)&Xhi,     g_Xhi);
    cudaGetSymbolAddress((void**)&Xlo,     g_Xlo);
    cudaGetSymbolAddress((void**)&Ihi,     g_Ihi);
    cudaGetSymbolAddress((void**)&Ilo,     g_Ilo);
    cudaGetSymbolAddress((void**)&WinT_hi, g_WinT_hi);
    cudaGetSymbolAddress((void**)&WinT_lo, g_WinT_lo);
    cudaGetSymbolAddress((void**)&WbT_hi,  g_WbT_hi);
    cudaGetSymbolAddress((void**)&WbT_lo,  g_WbT_lo);

    cudaFuncSetAttribute(mma_gemm<true,  true >, cudaFuncAttributeMaxDynamicSharedMemorySize, MG_SMEM);
    cudaFuncSetAttribute(mma_gemm<false, false>, cudaFuncAttributeMaxDynamicSharedMemorySize, MG_SMEM);

    const dim3 bs(256);

    // weight-space precompute (fp32-exact, small)
    vec_pre_k<<<1, 512>>>(Wo, bv, br, bo, Wk, bq, gv, bias2);
    wpre_k<<<dim3(8, 8, 3), bs>>>(Wq, Wk, Wv, Wr, Wo, Wqk, Wvo, Wro);

    // transpose + bf16-split weights
    dim3 tb32(32, 32), tg(16, 16);
    tsplit_k<<<tg, tb32>>>(Win, WinT_hi, WinT_lo, 0);
    tsplit_k<<<tg, tb32>>>(Wqk, WbT_hi, WbT_lo, 0);
    tsplit_k<<<tg, tb32>>>(Wvo, WbT_hi, WbT_lo, 512);
    tsplit_k<<<tg, tb32>>>(Wro, WbT_hi, WbT_lo, 1024);

    // split activations
    const int n4 = MTOT * D_DIM / 4;
    split_k<<<(n4 + 255) / 256, 256>>>(inp, Ihi, Ilo, n4);

    // big GEMMs on tensor cores (mma.sync bf16, 3-term split)
    mma_gemm<true,  true ><<<dim3(4, 256),  bs, MG_SMEM>>>(Ihi, Ilo, WinT_hi, WinT_lo,
                                                           bin, X, Xhi, Xlo, 512);
    mma_gemm<false, false><<<dim3(12, 256), bs, MG_SMEM>>>(Xhi, Xlo, WbT_hi, WbT_lo,
                                                           bias2, TVR, nullptr, nullptr, NTVR);

    // attention + epilogue
    attn_k<<<NBATCH, bs>>>(X, TVR, gv, out);
}